// round 17
// baseline (speedup 1.0000x reference)
#include <cuda_runtime.h>
#include <cuda_fp16.h>
#include <math.h>
#include <stdint.h>

#define B_   4
#define L_   2048
#define D_   256
#define H_   4
#define NL_  4
#define V_   32000
#define DH_  64
#define FF_  (4*D_)
#define MTOK (B_*L_)

// ---------------- scratch (allocation-free: __device__ globals) ----------------
__device__ float g_x [MTOK*D_];
__device__ float g_xn[MTOK*D_];
__device__ float g_q [MTOK*D_];
__device__ float g_k [MTOK*D_];
__device__ float g_v [MTOK*D_];
__device__ __half g_q16[MTOK*D_];                // rope'd q, 0.125-scaled, [tok][dim]
__device__ __half g_k16[MTOK*D_];                // rope'd k, [tok][dim]
__device__ __half g_v16t[B_*H_*DH_*L_];          // v transposed: [(b*H+h)*DH+d][tok]
__device__ __half g_xn16[MTOK*D_];               // rms out, fp16 pair-permuted
__device__ __half g_at16[MTOK*D_];               // attn out, fp16 pair-permuted
__device__ __half g_ff16[MTOK*FF_];              // silu out, fp16 pair-permuted
__device__ __half g_w16[(size_t)V_*D_];          // LM weight
__device__ __half g_wq16[NL_*D_*D_];
__device__ __half g_wk16[NL_*D_*D_];
__device__ __half g_wv16[NL_*D_*D_];
__device__ __half g_wo16[NL_*D_*D_];
__device__ __half g_wf1[NL_*FF_*D_];
__device__ __half g_wf2[NL_*D_*FF_];

// ---------------- helpers ----------------
__device__ __forceinline__ uint32_t smem_u32(const void* p) {
    uint32_t a;
    asm("{ .reg .u64 t; cvta.to.shared.u64 t, %1; cvt.u32.u64 %0, t; }" : "=r"(a) : "l"(p));
    return a;
}
#define CP_ASYNC16(dst_u32, src_ptr) \
    asm volatile("cp.async.cg.shared.global [%0], [%1], 16;" :: "r"(dst_u32), "l"(src_ptr))
#define CP_COMMIT() asm volatile("cp.async.commit_group;" ::: "memory")
#define CP_WAIT1()  asm volatile("cp.async.wait_group 1;" ::: "memory")

__device__ __forceinline__ int kperm16(int kk) {   // kk in [0,32)
    int p = kk >> 1;
    int pos = 4 * (p & 3) + (p >> 2);
    return pos * 2 + (kk & 1);
}

// ---------------- fused weight conversion (all 7 tensors, one launch) ----------------
#define NWQ (NL_*D_*D_)
#define NWF (NL_*FF_*D_)
#define NLM (V_*D_)
__global__ void cvt_all_k(const float* __restrict__ wq,  const float* __restrict__ wk,
                          const float* __restrict__ wv,  const float* __restrict__ wo,
                          const float* __restrict__ wf1, const float* __restrict__ wf2,
                          const float* __restrict__ lm,
                          __half* __restrict__ oq,  __half* __restrict__ ok,
                          __half* __restrict__ ov,  __half* __restrict__ oo,
                          __half* __restrict__ of1, __half* __restrict__ of2,
                          __half* __restrict__ olm) {
    long i = (long)blockIdx.x * 256 + threadIdx.x;
    const float* src; __half* dst; long j;
    if (i < NWQ)                    { src = wq;  dst = oq;  j = i; }
    else if (i < 2L*NWQ)            { src = wk;  dst = ok;  j = i - NWQ; }
    else if (i < 3L*NWQ)            { src = wv;  dst = ov;  j = i - 2L*NWQ; }
    else if (i < 4L*NWQ)            { src = wo;  dst = oo;  j = i - 3L*NWQ; }
    else if (i < 4L*NWQ + NWF)      { src = wf1; dst = of1; j = i - 4L*NWQ; }
    else if (i < 4L*NWQ + 2L*NWF)   { src = wf2; dst = of2; j = i - 4L*NWQ - NWF; }
    else                            { src = lm;  dst = olm; j = i - 4L*NWQ - 2L*NWF; }
    dst[(j & ~31L) | kperm16((int)(j & 31))] = __float2half(src[j]);
}
#define CVT_ALL_TOTAL (4L*NWQ + 2L*NWF + NLM)

// activation converter (LM input)
__global__ void cvt_f16_perm(const float* __restrict__ x, __half* __restrict__ o) {
    int i = blockIdx.x * 256 + threadIdx.x;
    o[(i & ~31) | kperm16(i & 31)] = __float2half(x[i]);
}

// ---------------- embedding ----------------
__global__ void embed_k(const int* __restrict__ ids, const int* __restrict__ tys,
                        const float* __restrict__ tok_emb, const float* __restrict__ type_emb,
                        float* __restrict__ x) {
    int i = blockIdx.x * 256 + threadIdx.x;
    int t = i / D_, d = i - t * D_;
    x[i] = tok_emb[(size_t)ids[t] * D_ + d] + type_emb[tys[t] * D_ + d];
}

// ---------------- RMSNorm: warp per row, 8 rows per block ----------------
__global__ void rms_k(const float* __restrict__ x, const float* __restrict__ w,
                      float* __restrict__ y, __half* __restrict__ y16) {
    int row = blockIdx.x * 8 + (threadIdx.x >> 5);
    int lane = threadIdx.x & 31;
    const float* xr = x + (size_t)row * D_;
    float4 a = *(const float4*)(xr + lane * 8);
    float4 b = *(const float4*)(xr + lane * 8 + 4);
    float s = a.x * a.x + a.y * a.y + a.z * a.z + a.w * a.w
            + b.x * b.x + b.y * b.y + b.z * b.z + b.w * b.w;
    #pragma unroll
    for (int o = 16; o; o >>= 1) s += __shfl_xor_sync(0xFFFFFFFFu, s, o);
    float r = rsqrtf(s * (1.0f / D_) + 1.1920929e-07f);
    float xv[8] = {a.x, a.y, a.z, a.w, b.x, b.y, b.z, b.w};
    float4 w0 = *(const float4*)(w + lane * 8);
    float4 w1 = *(const float4*)(w + lane * 8 + 4);
    float wv[8] = {w0.x, w0.y, w0.z, w0.w, w1.x, w1.y, w1.z, w1.w};
    float ov[8];
    #pragma unroll
    for (int j = 0; j < 8; j++) ov[j] = xv[j] * r * wv[j];
    *(float4*)(y + (size_t)row * D_ + lane * 8)     = make_float4(ov[0], ov[1], ov[2], ov[3]);
    *(float4*)(y + (size_t)row * D_ + lane * 8 + 4) = make_float4(ov[4], ov[5], ov[6], ov[7]);
    #pragma unroll
    for (int j = 0; j < 8; j++) {
        int d = lane * 8 + j;
        y16[(size_t)row * D_ + (d & ~31) + kperm16(d & 31)] = __float2half(ov[j]);
    }
}

// ---------------- fused RoPE->fp16 + V transpose-convert (grid-partitioned) ----------------
#define ROPE_BLKS (MTOK * H_ * 32 / 256)          // 4096
#define VT_BLKS_X (MTOK / 32)                     // 256
#define VT_BLKS   (VT_BLKS_X * (D_ / 32))         // 2048
__global__ void ropevt_k(const float* __restrict__ q, const float* __restrict__ k,
                         const float* __restrict__ v,
                         __half* __restrict__ q16, __half* __restrict__ k16,
                         __half* __restrict__ vt) {
    __shared__ float tile[32][33];
    if (blockIdx.x < ROPE_BLKS) {
        int i = blockIdx.x * 256 + threadIdx.x;
        int j  = i & 31;
        int hh = (i >> 5) & (H_ - 1);
        int t  = i >> 7;
        int pos = t & (L_ - 1);
        float freq = expf(-logf(10000.0f) * (float)j * (1.0f / 32.0f));
        float ang = (float)pos * freq;
        float c = cosf(ang), s = sinf(ang);
        size_t base = (size_t)t * D_ + hh * DH_ + j;
        float q0 = q[base], q1 = q[base + 32];
        q16[base]      = __float2half((q0 * c - q1 * s) * 0.125f);
        q16[base + 32] = __float2half((q1 * c + q0 * s) * 0.125f);
        float k0 = k[base], k1 = k[base + 32];
        k16[base]      = __float2half(k0 * c - k1 * s);
        k16[base + 32] = __float2half(k1 * c + k0 * s);
    } else {
        int bx = blockIdx.x - ROPE_BLKS;
        int t0 = (bx % VT_BLKS_X) * 32;
        int d0 = (bx / VT_BLKS_X) * 32;
        int tx = threadIdx.x & 31, ty = threadIdx.x >> 5;
        #pragma unroll
        for (int u = 0; u < 4; u++)
            tile[ty + u * 8][tx] = v[(size_t)(t0 + ty + u * 8) * D_ + d0 + tx];
        __syncthreads();
        int b = t0 / L_;
        int h = d0 / DH_;
        int dl = d0 % DH_;
        #pragma unroll
        for (int u = 0; u < 4; u++) {
            int d = dl + ty + u * 8;
            vt[((size_t)(b * H_ + h) * DH_ + d) * L_ + (t0 % L_) + tx] =
                __float2half(tile[tx][ty + u * 8]);
        }
    }
}

// ---------------- tensor-core flash attention (fp16 in; fp16 permuted out) ----------------
#define MMA16(cc, a0, a1, a2, a3, bb0, bb1) \
    asm volatile("mma.sync.aligned.m16n8k16.row.col.f32.f16.f16.f32 " \
                 "{%0,%1,%2,%3}, {%4,%5,%6,%7}, {%8,%9}, {%0,%1,%2,%3};\n" \
                 : "+f"((cc)[0]), "+f"((cc)[1]), "+f"((cc)[2]), "+f"((cc)[3]) \
                 : "r"(a0), "r"(a1), "r"(a2), "r"(a3), "r"(bb0), "r"(bb1))

__device__ __forceinline__ unsigned f2h2(float a, float b) {
    __half2 h = __floats2half2_rn(a, b);
    return *(unsigned*)&h;
}

__global__ void __launch_bounds__(128) attn_tc(const __half* __restrict__ q16,
                                               const __half* __restrict__ k16,
                                               const __half* __restrict__ v16t,
                                               const int* __restrict__ am,
                                               __half* __restrict__ out16) {
    const int h = blockIdx.y, b = blockIdx.z;
    const int tid = threadIdx.x, warp = tid >> 5, lane = tid & 31;
    const int g = lane >> 2, t4 = lane & 3;

    __shared__ __half Ks[64][72];
    __shared__ __half Vt[64][72];
    __shared__ int Ms[64];

    for (int hf = 0; hf < 2; hf++) {
        const int qt = (hf == 0) ? (int)(gridDim.x * 2 - 1 - blockIdx.x) : (int)blockIdx.x;
        const int rl0 = warp * 16 + g;
        const int rl1 = rl0 + 8;

        unsigned qa[4][4];
        {
            size_t qr0 = ((size_t)(b * L_) + qt * 64 + rl0) * D_ + h * DH_;
            size_t qr1 = qr0 + 8 * (size_t)D_;
            #pragma unroll
            for (int ks = 0; ks < 4; ks++) {
                int d0 = ks * 16 + t4 * 2;
                qa[ks][0] = *(const unsigned*)(q16 + qr0 + d0);
                qa[ks][1] = *(const unsigned*)(q16 + qr1 + d0);
                qa[ks][2] = *(const unsigned*)(q16 + qr0 + d0 + 8);
                qa[ks][3] = *(const unsigned*)(q16 + qr1 + d0 + 8);
            }
        }

        float m0 = -1e30f, m1 = -1e30f, l0 = 0.0f, l1 = 0.0f;
        float oa[8][4];
        #pragma unroll
        for (int dt = 0; dt < 8; dt++)
            #pragma unroll
            for (int f = 0; f < 4; f++) oa[dt][f] = 0.0f;

        for (int kt = 0; kt <= qt; kt++) {
            {
                int key = tid >> 1, hseg = (tid & 1) * 32;
                const uint4* src = (const uint4*)(k16 + ((size_t)(b * L_) + kt * 64 + key) * D_
                                                  + h * DH_ + hseg);
                uint4* dst = (uint4*)&Ks[key][hseg];
                #pragma unroll
                for (int u = 0; u < 4; u++) dst[u] = src[u];
                int d = tid >> 1;
                const uint4* vs = (const uint4*)(v16t + ((size_t)(b * H_ + h) * DH_ + d) * L_
                                                 + kt * 64 + hseg);
                uint4* vd = (uint4*)&Vt[d][hseg];
                #pragma unroll
                for (int u = 0; u < 4; u++) vd[u] = vs[u];
                if (tid < 64) Ms[tid] = am[b * L_ + kt * 64 + tid];
            }
            __syncthreads();

            float sac[8][4];
            #pragma unroll
            for (int nt = 0; nt < 8; nt++)
                #pragma unroll
                for (int f = 0; f < 4; f++) sac[nt][f] = 0.0f;
            #pragma unroll
            for (int nt = 0; nt < 8; nt++) {
                #pragma unroll
                for (int ks = 0; ks < 4; ks++) {
                    unsigned bb0 = *(const unsigned*)&Ks[nt * 8 + g][ks * 16 + t4 * 2];
                    unsigned bb1 = *(const unsigned*)&Ks[nt * 8 + g][ks * 16 + t4 * 2 + 8];
                    MMA16(sac[nt], qa[ks][0], qa[ks][1], qa[ks][2], qa[ks][3], bb0, bb1);
                }
            }

            const bool last = (kt == qt);
            float mx0 = -1e30f, mx1 = -1e30f;
            #pragma unroll
            for (int nt = 0; nt < 8; nt++) {
                int c0 = nt * 8 + t4 * 2, c1 = c0 + 1;
                bool p0 = Ms[c0] != 0, p1 = Ms[c1] != 0;
                sac[nt][0] = (p0 && (!last || c0 <= rl0)) ? sac[nt][0] : -1e30f;
                sac[nt][1] = (p1 && (!last || c1 <= rl0)) ? sac[nt][1] : -1e30f;
                sac[nt][2] = (p0 && (!last || c0 <= rl1)) ? sac[nt][2] : -1e30f;
                sac[nt][3] = (p1 && (!last || c1 <= rl1)) ? sac[nt][3] : -1e30f;
                mx0 = fmaxf(mx0, fmaxf(sac[nt][0], sac[nt][1]));
                mx1 = fmaxf(mx1, fmaxf(sac[nt][2], sac[nt][3]));
            }
            mx0 = fmaxf(mx0, __shfl_xor_sync(0xFFFFFFFFu, mx0, 1));
            mx0 = fmaxf(mx0, __shfl_xor_sync(0xFFFFFFFFu, mx0, 2));
            mx1 = fmaxf(mx1, __shfl_xor_sync(0xFFFFFFFFu, mx1, 1));
            mx1 = fmaxf(mx1, __shfl_xor_sync(0xFFFFFFFFu, mx1, 2));
            float mn0 = fmaxf(m0, mx0), mn1 = fmaxf(m1, mx1);
            float sc0 = __expf(m0 - mn0), sc1 = __expf(m1 - mn1);
            m0 = mn0; m1 = mn1;

            float rs0 = 0.0f, rs1 = 0.0f;
            #pragma unroll
            for (int nt = 0; nt < 8; nt++) {
                sac[nt][0] = (sac[nt][0] > -1e29f) ? __expf(sac[nt][0] - m0) : 0.0f;
                sac[nt][1] = (sac[nt][1] > -1e29f) ? __expf(sac[nt][1] - m0) : 0.0f;
                sac[nt][2] = (sac[nt][2] > -1e29f) ? __expf(sac[nt][2] - m1) : 0.0f;
                sac[nt][3] = (sac[nt][3] > -1e29f) ? __expf(sac[nt][3] - m1) : 0.0f;
                rs0 += sac[nt][0] + sac[nt][1];
                rs1 += sac[nt][2] + sac[nt][3];
            }
            rs0 += __shfl_xor_sync(0xFFFFFFFFu, rs0, 1);
            rs0 += __shfl_xor_sync(0xFFFFFFFFu, rs0, 2);
            rs1 += __shfl_xor_sync(0xFFFFFFFFu, rs1, 1);
            rs1 += __shfl_xor_sync(0xFFFFFFFFu, rs1, 2);
            l0 = l0 * sc0 + rs0;
            l1 = l1 * sc1 + rs1;
            #pragma unroll
            for (int dt = 0; dt < 8; dt++) {
                oa[dt][0] *= sc0; oa[dt][1] *= sc0;
                oa[dt][2] *= sc1; oa[dt][3] *= sc1;
            }

            unsigned pa[4][4];
            #pragma unroll
            for (int kp = 0; kp < 4; kp++) {
                pa[kp][0] = f2h2(sac[2 * kp][0],     sac[2 * kp][1]);
                pa[kp][1] = f2h2(sac[2 * kp][2],     sac[2 * kp][3]);
                pa[kp][2] = f2h2(sac[2 * kp + 1][0], sac[2 * kp + 1][1]);
                pa[kp][3] = f2h2(sac[2 * kp + 1][2], sac[2 * kp + 1][3]);
            }
            #pragma unroll
            for (int dt = 0; dt < 8; dt++) {
                #pragma unroll
                for (int kp = 0; kp < 4; kp++) {
                    unsigned bb0 = *(const unsigned*)&Vt[dt * 8 + g][kp * 16 + t4 * 2];
                    unsigned bb1 = *(const unsigned*)&Vt[dt * 8 + g][kp * 16 + t4 * 2 + 8];
                    MMA16(oa[dt], pa[kp][0], pa[kp][1], pa[kp][2], pa[kp][3], bb0, bb1);
                }
            }
            __syncthreads();
        }

        float inv0 = (l0 > 0.0f) ? (1.0f / l0) : 0.0f;
        float inv1 = (l1 > 0.0f) ? (1.0f / l1) : 0.0f;
        size_t tok0 = (size_t)(b * L_) + qt * 64 + rl0;
        #pragma unroll
        for (int dt = 0; dt < 8; dt++) {
            int d = h * DH_ + dt * 8 + t4 * 2;
            int dp = (d & ~31) + kperm16(d & 31);
            *(__half2*)&out16[tok0 * D_ + dp] =
                __floats2half2_rn(oa[dt][0] * inv0, oa[dt][1] * inv0);
            *(__half2*)&out16[(tok0 + 8) * D_ + dp] =
                __floats2half2_rn(oa[dt][2] * inv1, oa[dt][3] * inv1);
        }
    }
}

// ---------------- fp16 tensor-core GEMM body (shared by all GEMMs) ----------------
template <int EPI>
__device__ __forceinline__ void gemm16_body(const __half* __restrict__ A,
                                            const __half* __restrict__ W,
                                            const float* __restrict__ R,
                                            float* __restrict__ C,
                                            __half* __restrict__ C16,
                                            int N, int K, int bm, int bn,
                                            __half* sh16) {
    const uint32_t sb = smem_u32(sh16);
    const int tid = threadIdx.x;
    const int warp = tid >> 5, lane = tid & 31;
    const int wm = warp >> 2, wn = warp & 3;
    const int gid = lane >> 2, qid = lane & 3;
    const int nchunks = K >> 5;

    auto issue = [&](int ch, int s) {
        const uint32_t abase = sb + (uint32_t)(s * 8192) * 2u;
        const uint32_t wbase = abase + 4096u * 2u;
        #pragma unroll
        for (int t = 0; t < 2; t++) {
            int c2 = tid + t * 256;
            int row = c2 >> 2, seg = (c2 & 3) << 3;
            uint32_t dst = (uint32_t)(row * 32 + seg) * 2u;
            CP_ASYNC16(abase + dst, A + (size_t)(bm + row) * K + ch * 32 + seg);
            CP_ASYNC16(wbase + dst, W + (size_t)(bn + row) * K + ch * 32 + seg);
        }
    };

    float cacc[4][4][4];
    #pragma unroll
    for (int i = 0; i < 4; i++)
        #pragma unroll
        for (int j = 0; j < 4; j++)
            #pragma unroll
            for (int f = 0; f < 4; f++) cacc[i][j][f] = 0.0f;

    issue(0, 0); CP_COMMIT();
    issue(1, 1); CP_COMMIT();

    for (int ch = 0; ch < nchunks; ch++) {
        const int s = ch % 3;
        CP_WAIT1();
        __syncthreads();
        if (ch + 2 < nchunks) {
            issue(ch + 2, (ch + 2) % 3);
            CP_COMMIT();
        }
        const __half* Ab = sh16 + s * 8192;
        const __half* Wb = Ab + 4096;

        uint4 bb[4];
        #pragma unroll
        for (int nt = 0; nt < 4; nt++) {
            int rn = wn * 32 + nt * 8 + gid;
            bb[nt] = *(const uint4*)&Wb[rn * 32 + qid * 8];
        }
        #pragma unroll
        for (int mt = 0; mt < 4; mt++) {
            int r0 = wm * 64 + mt * 16 + gid;
            uint4 lo = *(const uint4*)&Ab[r0 * 32 + qid * 8];
            uint4 hi = *(const uint4*)&Ab[(r0 + 8) * 32 + qid * 8];
            #pragma unroll
            for (int nt = 0; nt < 4; nt++) {
                asm volatile(
                    "mma.sync.aligned.m16n8k16.row.col.f32.f16.f16.f32 "
                    "{%0,%1,%2,%3}, {%4,%5,%6,%7}, {%8,%9}, {%0,%1,%2,%3};\n"
                    : "+f"(cacc[mt][nt][0]), "+f"(cacc[mt][nt][1]),
                      "+f"(cacc[mt][nt][2]), "+f"(cacc[mt][nt][3])
                    : "r"(lo.x), "r"(hi.x), "r"(lo.y), "r"(hi.y),
                      "r"(bb[nt].x), "r"(bb[nt].y));
                asm volatile(
                    "mma.sync.aligned.m16n8k16.row.col.f32.f16.f16.f32 "
                    "{%0,%1,%2,%3}, {%4,%5,%6,%7}, {%8,%9}, {%0,%1,%2,%3};\n"
                    : "+f"(cacc[mt][nt][0]), "+f"(cacc[mt][nt][1]),
                      "+f"(cacc[mt][nt][2]), "+f"(cacc[mt][nt][3])
                    : "r"(lo.z), "r"(hi.z), "r"(lo.w), "r"(hi.w),
                      "r"(bb[nt].z), "r"(bb[nt].w));
            }
        }
    }

    #pragma unroll
    for (int mt = 0; mt < 4; mt++) {
        int row = bm + wm * 64 + mt * 16 + gid;
        #pragma unroll
        for (int nt = 0; nt < 4; nt++) {
            int col = bn + wn * 32 + nt * 8 + qid * 2;
            float c0 = cacc[mt][nt][0], c1 = cacc[mt][nt][1];
            float c2 = cacc[mt][nt][2], c3 = cacc[mt][nt][3];
            if (EPI == 2) {
                c0 = c0 / (1.0f + __expf(-c0));
                c1 = c1 / (1.0f + __expf(-c1));
                c2 = c2 / (1.0f + __expf(-c2));
                c3 = c3 / (1.0f + __expf(-c3));
                int dp = (col & ~31) + kperm16(col & 31);
                *(__half2*)&C16[(size_t)row * N + dp] = __floats2half2_rn(c0, c1);
                *(__half2*)&C16[(size_t)(row + 8) * N + dp] = __floats2half2_rn(c2, c3);
            } else {
                if (EPI == 1) {
                    float2 r0v = *(const float2*)(R + (size_t)row * N + col);
                    float2 r1v = *(const float2*)(R + (size_t)(row + 8) * N + col);
                    c0 += r0v.x; c1 += r0v.y; c2 += r1v.x; c3 += r1v.y;
                }
                *(float2*)(C + (size_t)row * N + col) = make_float2(c0, c1);
                *(float2*)(C + (size_t)(row + 8) * N + col) = make_float2(c2, c3);
            }
        }
    }
}

template <int EPI>
__global__ void __launch_bounds__(256, 2) gemm_f16k(const __half* __restrict__ A,
                                                    const __half* __restrict__ W,
                                                    const float* __restrict__ R,
                                                    float* __restrict__ C,
                                                    __half* __restrict__ C16,
                                                    int N, int K) {
    extern __shared__ __half sh16[];
    gemm16_body<EPI>(A, W, R, C, C16, N, K, blockIdx.y * 128, blockIdx.x * 128, sh16);
}

__global__ void __launch_bounds__(256, 2) gemm_qkv16(const __half* __restrict__ A,
                                                     const __half* __restrict__ Wq,
                                                     const __half* __restrict__ Wk,
                                                     const __half* __restrict__ Wv,
                                                     float* __restrict__ q,
                                                     float* __restrict__ kk,
                                                     float* __restrict__ vv) {
    extern __shared__ __half sh16[];
    int sel = blockIdx.x >> 1;
    const __half* W = (sel == 0) ? Wq : (sel == 1) ? Wk : Wv;
    float*        C = (sel == 0) ? q  : (sel == 1) ? kk : vv;
    gemm16_body<0>(A, W, nullptr, C, nullptr, D_, D_,
                   blockIdx.y * 128, (blockIdx.x & 1) * 128, sh16);
}

__global__ void __launch_bounds__(256, 2) lm_f16(const __half* __restrict__ A,
                                                 const __half* __restrict__ W,
                                                 float* __restrict__ C,
                                                 int M, int N, int K) {
    extern __shared__ __half sh16[];
    gemm16_body<0>(A, W, nullptr, C, nullptr, N, K, blockIdx.y * 128, blockIdx.x * 128, sh16);
}

// ---------------- classifier heads on cls token (b, 0) ----------------
__global__ void heads_k(const float* __restrict__ xn,
                        const float* __restrict__ rw, const float* __restrict__ rb,
                        const float* __restrict__ mw, const float* __restrict__ mb,
                        float* __restrict__ out) {
    int b = blockIdx.x;
    int t = threadIdx.x;
    float xv = xn[((size_t)b * L_) * D_ + t];
    float pr = xv * rw[t];
    float pm = xv * mw[t];
    __shared__ float sr[8], sm_[8];
    #pragma unroll
    for (int o = 16; o; o >>= 1) {
        pr += __shfl_xor_sync(0xFFFFFFFFu, pr, o);
        pm += __shfl_xor_sync(0xFFFFFFFFu, pm, o);
    }
    if ((t & 31) == 0) { sr[t >> 5] = pr; sm_[t >> 5] = pm; }
    __syncthreads();
    if (t == 0) {
        float a = 0.0f, c = 0.0f;
        #pragma unroll
        for (int i = 0; i < 8; i++) { a += sr[i]; c += sm_[i]; }
        out[b]      = a + rb[0];
        out[B_ + b] = c + mb[0];
    }
}

// ---------------- driver ----------------
extern "C" void kernel_launch(void* const* d_in, const int* in_sizes, int n_in,
                              void* d_out, int out_size) {
    const int*   token_ids    = (const int*)  d_in[0];
    const int*   token_types  = (const int*)  d_in[1];
    const int*   amask        = (const int*)  d_in[2];
    const float* tok_emb      = (const float*)d_in[3];
    const float* type_emb     = (const float*)d_in[4];
    const float* norm1_w      = (const float*)d_in[5];
    const float* wq           = (const float*)d_in[6];
    const float* wk           = (const float*)d_in[7];
    const float* wv           = (const float*)d_in[8];
    const float* wo           = (const float*)d_in[9];
    const float* norm2_w      = (const float*)d_in[10];
    const float* ff_w1        = (const float*)d_in[11];
    const float* ff_w2        = (const float*)d_in[12];
    const float* final_norm_w = (const float*)d_in[13];
    const float* lm_w         = (const float*)d_in[14];
    const float* read_w       = (const float*)d_in[15];
    const float* read_b       = (const float*)d_in[16];
    const float* mort_w       = (const float*)d_in[17];
    const float* mort_b       = (const float*)d_in[18];
    float* out = (float*)d_out;

    float *x, *xn, *q, *k, *v;
    __half *q16, *k16, *v16t, *xn16, *at16, *ff16, *w16;
    __half *wq16, *wk16, *wv16, *wo16, *wf1, *wf2;
    cudaGetSymbolAddress((void**)&x,    g_x);
    cudaGetSymbolAddress((void**)&xn,   g_xn);
    cudaGetSymbolAddress((void**)&q,    g_q);
    cudaGetSymbolAddress((void**)&k,    g_k);
    cudaGetSymbolAddress((void**)&v,    g_v);
    cudaGetSymbolAddress((void**)&q16,  g_q16);
    cudaGetSymbolAddress((void**)&k16,  g_k16);
    cudaGetSymbolAddress((void**)&v16t, g_v16t);
    cudaGetSymbolAddress((void**)&xn16, g_xn16);
    cudaGetSymbolAddress((void**)&at16, g_at16);
    cudaGetSymbolAddress((void**)&ff16, g_ff16);
    cudaGetSymbolAddress((void**)&w16,  g_w16);
    cudaGetSymbolAddress((void**)&wq16, g_wq16);
    cudaGetSymbolAddress((void**)&wk16, g_wk16);
    cudaGetSymbolAddress((void**)&wv16, g_wv16);
    cudaGetSymbolAddress((void**)&wo16, g_wo16);
    cudaGetSymbolAddress((void**)&wf1,  g_wf1);
    cudaGetSymbolAddress((void**)&wf2,  g_wf2);

    cudaFuncSetAttribute(lm_f16,       cudaFuncAttributeMaxDynamicSharedMemorySize, 49152);
    cudaFuncSetAttribute(gemm_qkv16,   cudaFuncAttributeMaxDynamicSharedMemorySize, 49152);
    cudaFuncSetAttribute(gemm_f16k<1>, cudaFuncAttributeMaxDynamicSharedMemorySize, 49152);
    cudaFuncSetAttribute(gemm_f16k<2>, cudaFuncAttributeMaxDynamicSharedMemorySize, 49152);

    // all weights (incl. LM) -> fp16 pair-permuted, ONE launch
    cvt_all_k<<<(unsigned)((CVT_ALL_TOTAL + 255) / 256), 256>>>(
        wq, wk, wv, wo, ff_w1, ff_w2, lm_w,
        wq16, wk16, wv16, wo16, wf1, wf2, w16);

    embed_k<<<MTOK * D_ / 256, 256>>>(token_ids, token_types, tok_emb, type_emb, x);

    for (int li = 0; li < NL_; li++) {
        rms_k<<<MTOK / 8, 256>>>(x, norm1_w + li * D_, xn, xn16);
        gemm_qkv16<<<dim3(6, MTOK / 128), 256, 49152>>>(
            xn16, wq16 + li * D_ * D_, wk16 + li * D_ * D_, wv16 + li * D_ * D_, q, k, v);
        ropevt_k<<<ROPE_BLKS + VT_BLKS, 256>>>(q, k, v, q16, k16, v16t);
        attn_tc<<<dim3(L_ / 128, H_, B_), 128>>>(q16, k16, v16t, amask, at16);
        gemm_f16k<1><<<dim3(2, MTOK / 128), 256, 49152>>>(
            at16, wo16 + li * D_ * D_, x, x, nullptr, D_, D_);
        rms_k<<<MTOK / 8, 256>>>(x, norm2_w + li * D_, xn, xn16);
        gemm_f16k<2><<<dim3(8, MTOK / 128), 256, 49152>>>(
            xn16, wf1 + li * FF_ * D_, nullptr, nullptr, ff16, FF_, D_);
        gemm_f16k<1><<<dim3(2, MTOK / 128), 256, 49152>>>(
            ff16, wf2 + li * D_ * FF_, x, x, nullptr, D_, FF_);
    }
    rms_k<<<MTOK / 8, 256>>>(x, final_norm_w, xn, xn16);
    lm_f16<<<dim3(V_ / 128, MTOK / 128), 256, 49152>>>(xn16, w16, out, MTOK, V_, D_);
    heads_k<<<B_, 256>>>(xn, read_w, read_b, mort_w, mort_b, out + (size_t)MTOK * V_);
}